// round 17
// baseline (speedup 1.0000x reference)
#include <cuda_runtime.h>
#include <cstdint>
#include <math.h>

#define BATCH 4
#define HW 262144            // 512*512
#define NINST 32
#define NBX (1<<16)          // bins per class per sample
#define NSP 16               // scan chunks per row (NBX/SBLK)
#define SBLK 4096            // bins per scan chunk
#define BSCALE_N 8192.0f     // neg: x in [0,8) over 2^16 bins  -> 2^13
#define BSCALE_P 4096.0f     // pos: x in [0,16) over 2^16 bins -> 2^12
#define DXN (1.0f/8192.0f)
#define DXP (1.0f/4096.0f)
#define SSTR 32              // neg subsample stride == atomic weight
#define HBLK 256             // k_hist blocks per sample (HW/1024)
#define S4CH 64              // k_s4 chunks per row (1024 bins each)
#define S4BLK (S4CH*8)       // 512 blocks in k_s4

// ---------------- static device scratch ----------------
// All accumulators zero at module load; re-zeroed in-pipeline each run.
// g_hist zero at load; k_scan re-zeroes it behind itself each run.
__device__ double g_sum_e0[BATCH][NINST];
__device__ double g_sum_e1[BATCH][NINST];
__device__ double g_sum_sg[BATCH][NINST];
__device__ unsigned g_count[BATCH][NINST];
__device__ unsigned g_tick[BATCH];
__device__ unsigned g_tickS4;
__device__ double g_var[BATCH], g_loss[BATCH], g_suminv[BATCH];
__device__ float  g_Pf[BATCH];
// hist/pre layout: [cls*4 + b][NBX], cls 0 = negative (weighted), 1 = positive (exact)
__device__ __align__(256) unsigned g_hist[8u * NBX];
__device__ __align__(256) unsigned g_pre[8u * NBX];
__device__ unsigned long long g_spineF[8][NSP];   // bit32 = ready flag, low 32 = sum

// ---------------- packed f32x2 helpers ----------------
__device__ __forceinline__ unsigned long long pk2(float lo, float hi) {
    unsigned long long r;
    asm("mov.b64 %0, {%1, %2};" : "=l"(r) : "f"(lo), "f"(hi));
    return r;
}
__device__ __forceinline__ void upk2(float& lo, float& hi, unsigned long long v) {
    asm("mov.b64 {%0, %1}, %2;" : "=f"(lo), "=f"(hi) : "l"(v));
}
__device__ __forceinline__ unsigned long long fma2(unsigned long long a,
                                                   unsigned long long b,
                                                   unsigned long long c) {
    unsigned long long r;
    asm("fma.rn.f32x2 %0, %1, %2, %3;" : "=l"(r) : "l"(a), "l"(b), "l"(c));
    return r;
}

// ---------------- stats (vectorized, 4 px/thread) ----------------
__global__ void k_stats(const float* __restrict__ emb,
                        const float* __restrict__ sig,
                        const int* __restrict__ gt) {
    __shared__ float s0[8][NINST], s1[8][NINST], ss[8][NINST];
    __shared__ unsigned sc[8][NINST];
    int t = threadIdx.x;
    int b = blockIdx.x >> 8, blk = blockIdx.x & 255;
    int w = t >> 5, lane = t & 31;
    s0[w][lane] = 0.f; s1[w][lane] = 0.f; ss[w][lane] = 0.f; sc[w][lane] = 0u;
    __syncthreads();
    size_t p4 = (size_t)blk * 256 + t;         // float4 index
    float4 ve0 = reinterpret_cast<const float4*>(emb + (size_t)(b * 2 + 0) * HW)[p4];
    float4 ve1 = reinterpret_cast<const float4*>(emb + (size_t)(b * 2 + 1) * HW)[p4];
    float4 vys = reinterpret_cast<const float4*>(sig + (size_t)b * HW)[p4];
    int4   vg  = reinterpret_cast<const int4*>(gt + (size_t)b * HW)[p4];
    float e0a[4] = { ve0.x, ve0.y, ve0.z, ve0.w };
    float e1a[4] = { ve1.x, ve1.y, ve1.z, ve1.w };
    float ysa[4] = { vys.x, vys.y, vys.z, vys.w };
    int   ga[4]  = { vg.x, vg.y, vg.z, vg.w };
#pragma unroll
    for (int j = 0; j < 4; j++) {
        int g = ga[j];
        if (g > 0 && g <= NINST) {
            int n = g - 1;
            atomicAdd(&s0[w][n], e0a[j]);
            atomicAdd(&s1[w][n], e1a[j]);
            atomicAdd(&ss[w][n], ysa[j]);
            atomicAdd(&sc[w][n], 1u);
        }
    }
    __syncthreads();
    if (t < NINST) {
        float a0 = 0.f, a1 = 0.f, as = 0.f; unsigned ac = 0u;
#pragma unroll
        for (int i = 0; i < 8; i++) {
            a0 += s0[i][t]; a1 += s1[i][t]; as += ss[i][t]; ac += sc[i][t];
        }
        if (ac > 0u) {
            atomicAdd(&g_sum_e0[b][t], (double)a0);
            atomicAdd(&g_sum_e1[b][t], (double)a1);
            atomicAdd(&g_sum_sg[b][t], (double)as);
            atomicAdd(&g_count[b][t], ac);
        }
    }
}

// 4 pixels/thread; finalize fused (each block derives ABC from g_sum);
// negatives stratified-subsampled: pixel p takes ONLY instance n == p (mod 32),
// atomic weight 32. Positives exact. Fixup uses bit-identical FMA chain.
__global__ void k_hist(const float* __restrict__ emb,
                       const float* __restrict__ sig,
                       const int* __restrict__ gt) {
    __shared__ float4 sC[NINST];
    __shared__ float sSG[NINST];
    __shared__ ulonglong2 sPK[NINST][2];   // {Apk,B0pk} {B1pk,Cpk}
    __shared__ unsigned s_last;
    int t = threadIdx.x, b = blockIdx.y;

    if (t < NINST) {                       // ---- fused finalize (warp 0) ----
        unsigned cnt = g_count[b][t];
        double inv = (cnt > 0u) ? 1.0 / (double)cnt : 0.0;
        float c0 = (float)(g_sum_e0[b][t] * inv);
        float c1 = (float)(g_sum_e1[b][t] * inv);
        float sgm = (float)(g_sum_sg[b][t] * inv);
        sSG[t] = sgm;
        float4 v;
        if (cnt > 0u) {
            float A = (0.5f / (sgm * sgm)) * BSCALE_N;
            v.x = A; v.y = -2.0f * A * c0; v.z = -2.0f * A * c1;
            v.w = A * fmaf(c1, c1, c0 * c0);
        } else {
            v.x = 0.f; v.y = 0.f; v.z = 0.f; v.w = 3e30f;   // never binned, no NaN
        }
        sC[t] = v;
        sPK[t][0] = make_ulonglong2(pk2(v.x, v.x), pk2(v.y, v.y));
        sPK[t][1] = make_ulonglong2(pk2(v.z, v.z), pk2(v.w, v.w));
        unsigned Ps = cnt; double iv = inv;
        for (int o = 16; o; o >>= 1) {
            Ps += __shfl_down_sync(0xffffffffu, Ps, o);
            iv += __shfl_down_sync(0xffffffffu, iv, o);
        }
        if (blockIdx.x == 0 && t == 0) { g_Pf[b] = (float)Ps; g_suminv[b] = iv; }
    }
    __syncthreads();
    // ticket: last block per sample re-zeroes stats accumulators for next replay
    if (t == 0) s_last = atomicAdd(&g_tick[b], 1u);
    __syncthreads();
    if (s_last == HBLK - 1) {
        if (t < NINST) {
            g_sum_e0[b][t] = 0.0; g_sum_e1[b][t] = 0.0; g_sum_sg[b][t] = 0.0;
            g_count[b][t] = 0u;
        }
        if (t == 0) g_tick[b] = 0u;
    }

    int base = blockIdx.x * 1024 + t;
    const float* pe0 = emb + (size_t)(b * 2 + 0) * HW;
    const float* pe1 = emb + (size_t)(b * 2 + 1) * HW;
    const float* psg = sig + (size_t)b * HW;
    const int*   pgt = gt + (size_t)b * HW;

    float e0[4], e1[4], r2[4], ys[4];
    int gi[4];
#pragma unroll
    for (int j = 0; j < 4; j++) {
        int p = base + j * 256;               // p mod 32 == t mod 32 for all j
        e0[j] = pe0[p]; e1[j] = pe1[p]; ys[j] = psg[p];
        int g = pgt[p];
        gi[j] = (g > 0 && g <= NINST) ? g : 0;
        r2[j] = fmaf(e1[j], e1[j], e0[j] * e0[j]);
    }
    unsigned long long E0[2] = { pk2(e0[0], e0[1]), pk2(e0[2], e0[3]) };
    unsigned long long E1[2] = { pk2(e1[0], e1[1]), pk2(e1[2], e1[3]) };
    unsigned long long R2[2] = { pk2(r2[0], r2[1]), pk2(r2[2], r2[3]) };

    unsigned* hn = g_hist + ((size_t)b << 16);
    unsigned* hp = g_hist + ((size_t)(4 + b) << 16);
    int sb = t & (SSTR - 1);                  // sampled instance == lane id

    {
        ulonglong2 qa = sPK[sb][0];           // A, B0
        ulonglong2 qb = sPK[sb][1];           // B1, C
#pragma unroll
        for (int p = 0; p < 2; p++) {
            unsigned long long acc = fma2(qa.x, R2[p], qb.y);
            acc = fma2(qa.y, E0[p], acc);
            acc = fma2(qb.x, E1[p], acc);
            float x0, x1;
            upk2(x0, x1, acc);
            unsigned k0 = __float2uint_rz(x0);   // neg sat->0, huge sat->UINT_MAX
            unsigned k1 = __float2uint_rz(x1);
            if (k0 < NBX) atomicAdd(hn + k0, (unsigned)SSTR);
            if (k1 < NBX) atomicAdd(hn + k1, (unsigned)SSTR);
        }
    }

    // fixup + exact positive binning + var accumulation
    float var = 0.f;
#pragma unroll
    for (int j = 0; j < 4; j++) {
        if (gi[j] > 0) {
            int g = gi[j] - 1;
            float4 v = sC[g];
            float xs = fmaf(v.z, e1[j], fmaf(v.y, e0[j], fmaf(v.x, r2[j], v.w)));
            if (g == sb) {                    // was counted as negative above
                unsigned k = __float2uint_rz(xs);
                if (k < NBX) atomicAdd(hn + k, (unsigned)(-SSTR));
            }
            unsigned kp = __float2uint_rz(xs * 0.5f);   // BSCALE_P/BSCALE_N
            if (kp > NBX - 1) kp = NBX - 1;             // pos clamps to top bin
            atomicAdd(hp + kp, 1u);
            float d = ys[j] - sSG[g];
            var = fmaf(d, d, var);
        }
    }
    for (int o = 16; o; o >>= 1) var += __shfl_down_sync(0xffffffffu, var, o);
    __shared__ float wv[8];
    int lane = t & 31, w = t >> 5;
    if (lane == 0) wv[w] = var;
    __syncthreads();
    if (t == 0) {
        double s = 0;
        for (int i = 0; i < 8; i++) s += (double)wv[i];
        atomicAdd(&g_var[b], s);
    }
}

// ---------------- fused scan: chunk sums + decoupled lookback + prefix ----
// Also zeroes g_hist behind itself (hist data is in registers), so no clear
// pass is needed and k_s4 reads only g_pre.
__global__ void k_scan() {
    int y = blockIdx.y, c = blockIdx.x, t = threadIdx.x;
    size_t base = ((size_t)y << 16) + (size_t)c * SBLK + (size_t)t * 16;
    uint4* h = reinterpret_cast<uint4*>(g_hist + base);
    unsigned r[16];
    uint4 a;
    a = h[0]; r[0]=a.x; r[1]=a.y; r[2]=a.z; r[3]=a.w;
    a = h[1]; r[4]=a.x; r[5]=a.y; r[6]=a.z; r[7]=a.w;
    a = h[2]; r[8]=a.x; r[9]=a.y; r[10]=a.z; r[11]=a.w;
    a = h[3]; r[12]=a.x; r[13]=a.y; r[14]=a.z; r[15]=a.w;
    // zero hist for next replay (data now in registers)
    uint4 z = make_uint4(0u, 0u, 0u, 0u);
    h[0] = z; h[1] = z; h[2] = z; h[3] = z;
    unsigned tsum = 0;
#pragma unroll
    for (int j = 0; j < 16; j++) tsum += r[j];
    int lane = t & 31, w = t >> 5;
    unsigned inc = tsum;
    for (int o = 1; o < 32; o <<= 1) {
        unsigned v = __shfl_up_sync(0xffffffffu, inc, o);
        if (lane >= o) inc += v;
    }
    __shared__ unsigned ws[8];
    __shared__ unsigned s_pre;
    if (lane == 31) ws[w] = inc;
    __syncthreads();
    if (t == 0) {
        unsigned s = 0;
        for (int i = 0; i < 8; i++) { unsigned v = ws[i]; ws[i] = s; s += v; }
        atomicExch(&g_spineF[y][c], (1ULL << 32) | (unsigned long long)s);
    }
    if (t < 32) {
        unsigned sv = 0;
        if (t < c) {
            unsigned long long v;
            do { v = *((volatile unsigned long long*)&g_spineF[y][t]); }
            while (!(v >> 32));
            sv = (unsigned)v;
        }
        for (int o = 16; o; o >>= 1) sv += __shfl_down_sync(0xffffffffu, sv, o);
        if (t == 0) s_pre = sv;
    }
    __syncthreads();
    unsigned run = s_pre + ws[w] + (inc - tsum);
#pragma unroll
    for (int j = 0; j < 16; j++) { run += r[j]; r[j] = run; }
    uint4* p = reinterpret_cast<uint4*>(g_pre + base);
    p[0] = make_uint4(r[0], r[1], r[2], r[3]);
    p[1] = make_uint4(r[4], r[5], r[6], r[7]);
    p[2] = make_uint4(r[8], r[9], r[10], r[11]);
    p[3] = make_uint4(r[12], r[13], r[14], r[15]);
}

// fast 1 - e^{-x}
__device__ __forceinline__ float fast_em1(float x) {
    if (x < 1e-3f) return x * (1.0f - 0.5f * x);   // Taylor, rel err < x^2/6
    return 1.0f - __expf(-x);
}

// per-bucket closed-form Lovasz contributions (all-float fast path) + fused final.
// Reads ONLY g_pre; bucket mass m reconstructed by CDF difference.
__global__ void k_s4(float* __restrict__ out) {
    int y = blockIdx.y, t = threadIdx.x;
    int cls = y >> 2, b = y & 3;
    unsigned kbin0 = (unsigned)blockIdx.x * 1024u + (unsigned)t * 4u;
    size_t base = ((size_t)y << 16) + kbin0;
    uint4 qp = *reinterpret_cast<const uint4*>(g_pre + base);
    unsigned prev = (kbin0 == 0u) ? 0u : g_pre[base - 1];   // CDF before our bins
    unsigned p[4] = { qp.x, qp.y, qp.z, qp.w };
    unsigned r[4] = { qp.x - prev, qp.y - qp.x, qp.z - qp.y, qp.w - qp.z };

    float P = g_Pf[b];
    const unsigned* preNeg = g_pre + ((size_t)b << 16);
    const unsigned* prePos = g_pre + ((size_t)(4 + b) << 16);
    unsigned PT = prePos[NBX - 1];
    float acc = 0.0f;
#pragma unroll
    for (int j = 0; j < 4; j++) {
        unsigned m = r[j];
        if (!m) continue;
        float kb = (float)(kbin0 + (unsigned)j) + 0.5f;
        if (cls) {                               // positive bucket, x in [0,16)
            float x = kb * DXP;
            float em1 = fast_em1(x);             // 1 - e^{-x}
            float e = 2.0f * em1;                // e_pos
            float T = -__logf(em1);              // negs above: x_n < T
            int kT = (int)(T * BSCALE_N);
            if (kT < 0) kT = 0;
            if (kT > NBX - 1) kT = NBX - 1;
            float cn0 = (float)preNeg[kT];       // weighted neg count above
            acc += e * __fdividef((float)m, P + cn0);
        } else {                                 // negative bucket, x in [0,8)
            float x = kb * DXN;
            float e = 2.0f * __expf(-x);         // e_neg
            float em1 = fast_em1(x);
            float T = -__logf(em1);              // pos above: x_p > T
            int kT = (int)(T * BSCALE_P);
            if (kT < 0) kT = 0;
            if (kT > NBX - 1) kT = NBX - 1;
            float posAbove = (float)(PT - prePos[kT]);
            float cn0 = (float)(p[j] - m);       // weighted negs strictly before
            float u0 = P + cn0;
            acc += e * (P - posAbove) *
                   __fdividef((float)m, u0 * (u0 + (float)m));  // telescoped
        }
    }
    for (int o = 16; o; o >>= 1) acc += __shfl_down_sync(0xffffffffu, acc, o);
    __shared__ float wd[8];
    __shared__ unsigned s_last;
    int lane = t & 31, w = t >> 5;
    if (lane == 0) wd[w] = acc;
    __syncthreads();
    if (t == 0) {
        double s = 0;
        for (int i = 0; i < 8; i++) s += (double)wd[i];
        atomicAdd(&g_loss[b], s);
        __threadfence();
        s_last = atomicAdd(&g_tickS4, 1u);
    }
    __syncthreads();
    if (s_last == S4BLK - 1) {                  // ---- fused final (last block) ----
        if (t == 0) {
            double s = 0;
            for (int bb = 0; bb < BATCH; bb++)
                s += g_loss[bb] + g_var[bb] * g_suminv[bb] * (1.0 / 32.0);
            out[0] = (float)(s / (double)BATCH);
            g_tickS4 = 0u;
        }
        if (t < BATCH) { g_var[t] = 0.0; g_loss[t] = 0.0; }
        if (t < NSP * 8) g_spineF[t >> 4][t & (NSP - 1)] = 0ULL;  // 128 entries
    }
}

// ---------------- launch ----------------
extern "C" void kernel_launch(void* const* d_in, const int* in_sizes, int n_in,
                              void* d_out, int out_size) {
    const float* emb = (const float*)d_in[0];   // [4,2,512,512] f32
    const float* sig = (const float*)d_in[1];   // [4,1,512,512] f32
    const int*   gt  = (const int*)d_in[2];     // [4,1,512,512] int32
    float* out = (float*)d_out;

    k_stats<<<1024, 256>>>(emb, sig, gt);       // vectorized stats (no clear needed)
    k_hist<<<dim3(HBLK, BATCH), 256>>>(emb, sig, gt);   // 1 inst/px, weight 32
    k_scan<<<dim3(NSP, 8), 256>>>();            // prefix + self-clearing hist
    k_s4<<<dim3(S4CH, 8), 256>>>(out);          // pre-only loss + fused final
}